// round 14
// baseline (speedup 1.0000x reference)
#include <cuda_runtime.h>
#include <cuda_fp16.h>
#include <math.h>
#include <stdint.h>

#define H 1024
#define I 2048
#define E 8
#define TOPK 2
#define T 4096   // B*S

// ======================= scratch (static device globals) =====================
__device__ __align__(256) int   g_counts[E];
__device__ __align__(256) float g_probsum[E];
__device__ float g_zsum;
__device__ __align__(256) int   g_list[E * T];
__device__ __align__(256) float g_wlist[E * T];

__device__ __align__(256) __half g_xh[(size_t)T * H];
__device__ __align__(256) __half g_g[(size_t)E * H * I];
__device__ __align__(256) __half g_u[(size_t)E * H * I];
__device__ __align__(256) __half g_d[(size_t)E * I * H];
__device__ __align__(256) __half g_sg[(size_t)H * I];
__device__ __align__(256) __half g_su[(size_t)H * I];
__device__ __align__(256) __half g_sd[(size_t)I * H];
__device__ __align__(256) __half g_acth[(size_t)(E + 1) * T * I];

// ======================= PTX helpers ========================================
static __device__ __forceinline__ uint32_t s2u(const void* p) {
    uint32_t a;
    asm("{ .reg .u64 t; cvta.to.shared.u64 t, %1; cvt.u32.u64 %0, t; }"
        : "=r"(a) : "l"(p));
    return a;
}
static __device__ __forceinline__ void ldsm_x4(uint32_t& r0, uint32_t& r1,
                                               uint32_t& r2, uint32_t& r3,
                                               uint32_t addr) {
    asm volatile("ldmatrix.sync.aligned.m8n8.x4.shared.b16 {%0,%1,%2,%3}, [%4];"
                 : "=r"(r0), "=r"(r1), "=r"(r2), "=r"(r3) : "r"(addr));
}
static __device__ __forceinline__ void ldsm_x4t(uint32_t& r0, uint32_t& r1,
                                                uint32_t& r2, uint32_t& r3,
                                                uint32_t addr) {
    asm volatile("ldmatrix.sync.aligned.m8n8.x4.trans.shared.b16 {%0,%1,%2,%3}, [%4];"
                 : "=r"(r0), "=r"(r1), "=r"(r2), "=r"(r3) : "r"(addr));
}
static __device__ __forceinline__ void mma_f16(float* c, const uint32_t* a,
                                               uint32_t b0, uint32_t b1) {
    asm volatile(
        "mma.sync.aligned.m16n8k16.row.col.f32.f16.f16.f32 "
        "{%0,%1,%2,%3}, {%4,%5,%6,%7}, {%8,%9}, {%0,%1,%2,%3};"
        : "+f"(c[0]), "+f"(c[1]), "+f"(c[2]), "+f"(c[3])
        : "r"(a[0]), "r"(a[1]), "r"(a[2]), "r"(a[3]), "r"(b0), "r"(b1));
}
static __device__ __forceinline__ void cp16(uint32_t dst, const void* src,
                                            uint32_t sz) {
    asm volatile("cp.async.cg.shared.global [%0], [%1], 16, %2;"
                 :: "r"(dst), "l"(src), "r"(sz) : "memory");
}
static __device__ __forceinline__ void red_add_v2(float* p, float v0, float v1) {
    asm volatile("red.global.add.v2.f32 [%0], {%1, %2};"
                 :: "l"(p), "f"(v0), "f"(v1) : "memory");
}
#define CP_COMMIT() asm volatile("cp.async.commit_group;" ::: "memory")
#define CP_WAIT0()  asm volatile("cp.async.wait_group 0;" ::: "memory")

#define SWZ64(o)  ((uint32_t)(o) ^ ((((uint32_t)(o)) >> 3) & 0x30u))
#define SWZ128(o) ((uint32_t)(o) ^ ((((uint32_t)(o)) >> 3) & 0x70u))

// ======================= SMEM layouts (per stage) ===========================
#define GU_A      0
#define GU_BG     8192
#define GU_BU     12288
#define GU_STAGE  16384
#define GU_SMEM   (1024 + 4 * GU_STAGE)
#define DN_A      0
#define DN_B      16384
#define DN_STAGE  20480
#define DN_SMEM   (2048 + 4 * DN_STAGE)

// ======================= init / finalize ====================================
__global__ void init_kernel() {
    int i = threadIdx.x;
    if (i < E) { g_counts[i] = 0; g_probsum[i] = 0.f; }
    if (i == 0) g_zsum = 0.f;
}

__global__ void finalize_kernel(float* __restrict__ out) {
    if (threadIdx.x == 0) {
        float aux = 0.f;
#pragma unroll
        for (int e = 0; e < E; e++) {
            float tpe = (float)g_counts[e] / (float)(TOPK * T);
            float ppe = g_probsum[e] / (float)T;
            aux += tpe * ppe;
        }
        out[(size_t)T * H]     = (float)E * aux;
        out[(size_t)T * H + 1] = g_zsum / (float)T;
    }
}

// ======================= weight conversion (MLP-batched) =====================
static __device__ __forceinline__ void round8(const float4 a, const float4 b,
                                              __half* dh, size_t o) {
    __half2 h0 = __floats2half2_rn(a.x, a.y);
    __half2 h1 = __floats2half2_rn(a.z, a.w);
    __half2 h2 = __floats2half2_rn(b.x, b.y);
    __half2 h3 = __floats2half2_rn(b.z, b.w);
    uint4 uh;
    uh.x = *(const uint32_t*)&h0; uh.y = *(const uint32_t*)&h1;
    uh.z = *(const uint32_t*)&h2; uh.w = *(const uint32_t*)&h3;
    *reinterpret_cast<uint4*>(dh + o) = uh;
}

#define GW8 ((size_t)E * H * I / 8)     // float4-pairs per routed weight tensor
#define SW8 ((size_t)H * I / 8)
#define GUW_PAIRS (2 * GW8 + 2 * SW8)   // g, u, sg, su
#define DW_PAIRS  (GW8 + SW8)           // d, sd
#define GUW_BLK (GUW_PAIRS / 512)       // 2 pairs/thread
#define DW_BLK  (DW_PAIRS / 512)

// gate/up (+shared) weights -> fp16
__global__ void prep_w_gu_kernel(const float* __restrict__ gw,
                                 const float* __restrict__ uw,
                                 const float* __restrict__ sgw,
                                 const float* __restrict__ suw) {
    size_t pA = (size_t)blockIdx.x * 512 + threadIdx.x;
    size_t pB = pA + 256;
    const float *sA, *sB; __half *dA, *dB; size_t lA, lB;
    if (pA < GW8)            { sA = gw;  dA = g_g;  lA = pA; }
    else if (pA < 2 * GW8)   { sA = uw;  dA = g_u;  lA = pA - GW8; }
    else if (pA < 2 * GW8 + SW8) { sA = sgw; dA = g_sg; lA = pA - 2 * GW8; }
    else                     { sA = suw; dA = g_su; lA = pA - 2 * GW8 - SW8; }
    if (pB < GW8)            { sB = gw;  dB = g_g;  lB = pB; }
    else if (pB < 2 * GW8)   { sB = uw;  dB = g_u;  lB = pB - GW8; }
    else if (pB < 2 * GW8 + SW8) { sB = sgw; dB = g_sg; lB = pB - 2 * GW8; }
    else                     { sB = suw; dB = g_su; lB = pB - 2 * GW8 - SW8; }
    // all 4 loads in flight before any store
    float4 a0 = reinterpret_cast<const float4*>(sA)[lA * 2];
    float4 a1 = reinterpret_cast<const float4*>(sA)[lA * 2 + 1];
    float4 b0 = reinterpret_cast<const float4*>(sB)[lB * 2];
    float4 b1 = reinterpret_cast<const float4*>(sB)[lB * 2 + 1];
    round8(a0, a1, dA, lA * 8);
    round8(b0, b1, dB, lB * 8);
}

// down (+shared) weights -> fp16
__global__ void prep_w_d_kernel(const float* __restrict__ dw,
                                const float* __restrict__ sdw) {
    size_t pA = (size_t)blockIdx.x * 512 + threadIdx.x;
    size_t pB = pA + 256;
    const float *sA, *sB; __half *dA, *dB; size_t lA, lB;
    if (pA < GW8) { sA = dw;  dA = g_d;  lA = pA; }
    else          { sA = sdw; dA = g_sd; lA = pA - GW8; }
    if (pB < GW8) { sB = dw;  dB = g_d;  lB = pB; }
    else          { sB = sdw; dB = g_sd; lB = pB - GW8; }
    float4 a0 = reinterpret_cast<const float4*>(sA)[lA * 2];
    float4 a1 = reinterpret_cast<const float4*>(sA)[lA * 2 + 1];
    float4 b0 = reinterpret_cast<const float4*>(sB)[lB * 2];
    float4 b1 = reinterpret_cast<const float4*>(sB)[lB * 2 + 1];
    round8(a0, a1, dA, lA * 8);
    round8(b0, b1, dB, lB * 8);
}

// ======================= x-split + zero + router =============================
__global__ void prep_xr_kernel(const float* __restrict__ x,
                               const float* __restrict__ rw,
                               float* __restrict__ out) {
    const int b = blockIdx.x;
    const int tid = threadIdx.x;
    {
        size_t base = (size_t)b * 1024;   // pairs per block
        float4 v[8];
#pragma unroll
        for (int k = 0; k < 4; k++) {
            size_t p8 = base + tid + k * 256;
            v[2 * k]     = reinterpret_cast<const float4*>(x)[p8 * 2];
            v[2 * k + 1] = reinterpret_cast<const float4*>(x)[p8 * 2 + 1];
        }
        float4 z4 = make_float4(0.f, 0.f, 0.f, 0.f);
#pragma unroll
        for (int k = 0; k < 4; k++) {
            size_t p8 = base + tid + k * 256;
            round8(v[2 * k], v[2 * k + 1], g_xh, p8 * 8);
            reinterpret_cast<float4*>(out)[p8 * 2]     = z4;
            reinterpret_cast<float4*>(out)[p8 * 2 + 1] = z4;
        }
    }
    int t = b * 8 + (tid >> 5);
    int lane = tid & 31;
    const float* xr = x + (size_t)t * H;
    float* out_logits = out + (size_t)T * H + 2;

    float acc[E];
#pragma unroll
    for (int e = 0; e < E; e++) acc[e] = 0.f;
    for (int h = lane; h < H; h += 32) {
        float xv = xr[h];
        const float4* r4 = reinterpret_cast<const float4*>(rw + (size_t)h * E);
        float4 r0 = r4[0], r1 = r4[1];
        acc[0] += xv * r0.x; acc[1] += xv * r0.y;
        acc[2] += xv * r0.z; acc[3] += xv * r0.w;
        acc[4] += xv * r1.x; acc[5] += xv * r1.y;
        acc[6] += xv * r1.z; acc[7] += xv * r1.w;
    }
#pragma unroll
    for (int e = 0; e < E; e++)
#pragma unroll
        for (int off = 16; off > 0; off >>= 1)
            acc[e] += __shfl_xor_sync(0xffffffffu, acc[e], off);

    if (lane == 0) {
        float m = acc[0];
#pragma unroll
        for (int e = 1; e < E; e++) m = fmaxf(m, acc[e]);
        float p[E], s = 0.f;
#pragma unroll
        for (int e = 0; e < E; e++) { p[e] = expf(acc[e] - m); s += p[e]; }
        float inv = 1.f / s;
#pragma unroll
        for (int e = 0; e < E; e++) out_logits[(size_t)t * E + e] = acc[e];
        float lse = m + logf(s);
        atomicAdd(&g_zsum, lse * lse);
#pragma unroll
        for (int e = 0; e < E; e++) atomicAdd(&g_probsum[e], p[e] * inv);

        int e1 = 0;
#pragma unroll
        for (int e = 1; e < E; e++) if (acc[e] > acc[e1]) e1 = e;
        int e2 = (e1 == 0) ? 1 : 0;
#pragma unroll
        for (int e = 0; e < E; e++) if (e != e1 && acc[e] > acc[e2]) e2 = e;
        float p1 = p[e1] * inv, p2 = p[e2] * inv;
        float wn = 1.f / (p1 + p2);
        int pos1 = atomicAdd(&g_counts[e1], 1);
        g_list[e1 * T + pos1] = t;  g_wlist[e1 * T + pos1] = p1 * wn;
        int pos2 = atomicAdd(&g_counts[e2], 1);
        g_list[e2 * T + pos2] = t;  g_wlist[e2 * T + pos2] = p2 * wn;
    }
}

// ======================= GEMM 1: gate+up (plain fp16 HMMA) ===================
__global__ void __launch_bounds__(256, 2) mm_gateup_kernel() {
    extern __shared__ char smem[];
    const int e = blockIdx.z;
    const int cnt = (e < E) ? g_counts[e] : T;
    const int m0 = blockIdx.y * 128;
    if (m0 >= cnt) return;
    const int n0 = blockIdx.x * 64;
    const int tid = threadIdx.x;
    const int wid = tid >> 5;
    const int lane = tid & 31;

    int* rowTok = (int*)smem;
    if (tid < 128) {
        int slot = m0 + tid;
        rowTok[tid] = (slot < cnt) ? ((e < E) ? g_list[e * T + slot] : slot) : -1;
    }
    __syncthreads();

    const uint32_t sb = s2u(smem) + 1024;

    const __half* Gw = (e < E) ? g_g + (size_t)e * H * I : g_sg;
    const __half* Uw = (e < E) ? g_u + (size_t)e * H * I : g_su;

    const int u4 = tid & 3;
    const int rb = tid >> 2;
    const int tok0 = rowTok[rb];
    const int tok1 = rowTok[rb + 64];
    const size_t aG0 = (size_t)(tok0 >= 0 ? tok0 : 0) * H + u4 * 8;
    const size_t aG1 = (size_t)(tok1 >= 0 ? tok1 : 0) * H + u4 * 8;
    const uint32_t sz0 = (tok0 >= 0) ? 16u : 0u;
    const uint32_t sz1 = (tok1 >= 0) ? 16u : 0u;
    const uint32_t dA0 = SWZ64(rb * 64 + u4 * 16);
    const uint32_t dA1 = SWZ64((rb + 64) * 64 + u4 * 16);
    const int u8 = tid & 7;
    const int rbB = tid >> 3;
    const size_t bGsrc = (size_t)rbB * I + n0 + u8 * 8;
    const uint32_t dB = SWZ128(rbB * 128 + u8 * 16);

    auto load_stage = [&](int st, int c) {
        const int k0 = c * 32;
        const uint32_t bp = sb + st * GU_STAGE;
        cp16(bp + GU_A + dA0, g_xh + aG0 + k0, sz0);
        cp16(bp + GU_A + dA1, g_xh + aG1 + k0, sz1);
        size_t bo = bGsrc + (size_t)k0 * I;
        cp16(bp + GU_BG + dB, Gw + bo, 16);
        cp16(bp + GU_BU + dB, Uw + bo, 16);
    };

    float accG[2][4][4], accU[2][4][4];
#pragma unroll
    for (int i = 0; i < 2; i++)
#pragma unroll
        for (int j = 0; j < 4; j++)
#pragma unroll
            for (int q = 0; q < 4; q++) { accG[i][j][q] = 0.f; accU[i][j][q] = 0.f; }

    const int mw = (wid >> 1) * 32;
    const int nw = (wid & 1) * 32;
    const int arow_off = ((lane >> 3) & 1) * 8 + (lane & 7);
    const int akb_off = (lane >> 4) * 16;
    const int kloc = (lane & 7) + ((lane >> 3) & 1) * 8;
    const int noff = (lane >> 4) * 8;

    uint32_t aoff[2][2], boff[2][2];
#pragma unroll
    for (int i = 0; i < 2; i++)
#pragma unroll
        for (int kk = 0; kk < 2; kk++)
            aoff[i][kk] = SWZ64((mw + i * 16 + arow_off) * 64 + kk * 32 + akb_off);
#pragma unroll
    for (int jp = 0; jp < 2; jp++)
#pragma unroll
        for (int kk = 0; kk < 2; kk++)
            boff[jp][kk] = SWZ128((kk * 16 + kloc) * 128 + (nw + jp * 16 + noff) * 2);

    auto compute_stage = [&](int st) {
        const uint32_t bp = sb + st * GU_STAGE;
#pragma unroll
        for (int kk = 0; kk < 2; kk++) {
            uint32_t a[2][4];
            uint32_t gb[2][4], ub[2][4];
#pragma unroll
            for (int jp = 0; jp < 2; jp++) {
                ldsm_x4t(gb[jp][0], gb[jp][1], gb[jp][2], gb[jp][3], bp + GU_BG + boff[jp][kk]);
                ldsm_x4t(ub[jp][0], ub[jp][1], ub[jp][2], ub[jp][3], bp + GU_BU + boff[jp][kk]);
            }
#pragma unroll
            for (int i = 0; i < 2; i++)
                ldsm_x4(a[i][0], a[i][1], a[i][2], a[i][3], bp + GU_A + aoff[i][kk]);
#pragma unroll
            for (int i = 0; i < 2; i++)
#pragma unroll
                for (int jp = 0; jp < 2; jp++) {
                    mma_f16(accG[i][jp * 2 + 0], a[i], gb[jp][0], gb[jp][1]);
                    mma_f16(accG[i][jp * 2 + 1], a[i], gb[jp][2], gb[jp][3]);
                    mma_f16(accU[i][jp * 2 + 0], a[i], ub[jp][0], ub[jp][1]);
                    mma_f16(accU[i][jp * 2 + 1], a[i], ub[jp][2], ub[jp][3]);
                }
        }
    };

    const int NC = H / 32;  // 32 chunks, 16 pairs
    load_stage(0, 0); CP_COMMIT();
    load_stage(1, 1); CP_COMMIT();
    for (int c = 0; c < NC; c += 2) {
        CP_WAIT0();
        __syncthreads();
        if (c + 2 < NC) { load_stage((c + 2) & 3, c + 2); CP_COMMIT(); }
        compute_stage(c & 3);
        if (c + 3 < NC) { load_stage((c + 3) & 3, c + 3); CP_COMMIT(); }
        compute_stage((c + 1) & 3);
    }

    const int r4 = lane >> 2;
    const int cp2 = (lane & 3) * 2;
#pragma unroll
    for (int i = 0; i < 2; i++)
#pragma unroll
        for (int hh = 0; hh < 2; hh++) {
            int slot = m0 + mw + i * 16 + r4 + hh * 8;
            if (slot >= cnt) continue;
#pragma unroll
            for (int j = 0; j < 4; j++) {
                float g0 = accG[i][j][hh * 2 + 0], g1 = accG[i][j][hh * 2 + 1];
                float u0 = accU[i][j][hh * 2 + 0], u1 = accU[i][j][hh * 2 + 1];
                float v0 = g0 / (1.f + __expf(-g0)) * u0;
                float v1 = g1 / (1.f + __expf(-g1)) * u1;
                __half2 hp;
                hp.x = __float2half(v0); hp.y = __float2half(v1);
                int coln = nw + (j >> 1) * 16 + (j & 1) * 8 + cp2;
                size_t ai = (size_t)e * T * I + (size_t)slot * I + n0 + coln;
                *reinterpret_cast<__half2*>(g_acth + ai) = hp;
            }
        }
}

// ======================= GEMM 2: down (fused, M=256, warp 64x32) =============
__global__ void __launch_bounds__(256, 2) mm_down_kernel(float* __restrict__ out) {
    extern __shared__ char smem[];
    const int ez = blockIdx.z;
    const bool routed = (ez < E);
    const int cnt = routed ? g_counts[ez] : T;
    const int m0 = blockIdx.y * 256;
    if (m0 >= cnt) return;
    const int n0 = blockIdx.x * 64;
    const int tid = threadIdx.x;
    const int wid = tid >> 5;
    const int lane = tid & 31;

    int* tokSm = (int*)smem;
    float* wSm = (float*)(smem + 1024);
    {
        int slot = m0 + tid;
        if (routed) {
            tokSm[tid] = (slot < cnt) ? g_list[ez * T + slot] : 0;
            wSm[tid]   = (slot < cnt) ? g_wlist[ez * T + slot] : 0.f;
        } else {
            tokSm[tid] = slot;
            wSm[tid]   = 1.f;
        }
    }
    __syncthreads();

    const uint32_t sb = s2u(smem) + 2048;

    const __half* Bw = routed ? g_d + (size_t)ez * I * H : g_sd;
    const __half* Ah = g_acth + (size_t)ez * T * I;

    const int u4 = tid & 3;
    const int rb = tid >> 2;
    size_t aO[4];
    uint32_t szA[4], dA[4];
#pragma unroll
    for (int r = 0; r < 4; r++) {
        int row = rb + r * 64;
        int slot = m0 + row;
        aO[r]  = (size_t)(slot < cnt ? slot : 0) * I + u4 * 8;
        szA[r] = (slot < cnt) ? 16u : 0u;
        dA[r]  = SWZ64(row * 64 + u4 * 16);
    }
    const int u8 = tid & 7;
    const int rbB = tid >> 3;
    const size_t bSrc = (size_t)rbB * H + n0 + u8 * 8;
    const uint32_t dB = SWZ128(rbB * 128 + u8 * 16);

    auto load_stage = [&](int st, int c) {
        const int k0 = c * 32;
        const uint32_t bp = sb + st * DN_STAGE;
#pragma unroll
        for (int r = 0; r < 4; r++)
            cp16(bp + DN_A + dA[r], Ah + aO[r] + k0, szA[r]);
        size_t bo = bSrc + (size_t)k0 * H;
        cp16(bp + DN_B + dB, Bw + bo, 16);
    };

    float acc[4][4][4];
#pragma unroll
    for (int i = 0; i < 4; i++)
#pragma unroll
        for (int j = 0; j < 4; j++)
#pragma unroll
            for (int q = 0; q < 4; q++) acc[i][j][q] = 0.f;

    const int mw = (wid >> 1) * 64;
    const int nw = (wid & 1) * 32;
    const int arow_off = ((lane >> 3) & 1) * 8 + (lane & 7);
    const int akb_off = (lane >> 4) * 16;
    const int kloc = (lane & 7) + ((lane >> 3) & 1) * 8;
    const int noff = (lane >> 4) * 8;

    uint32_t aoff[4][2], boff[2][2];
#pragma unroll
    for (int i = 0; i < 4; i++)
#pragma unroll
        for (int kk = 0; kk < 2; kk++)
            aoff[i][kk] = SWZ64((mw + i * 16 + arow_off) * 64 + kk * 32 + akb_off);
#pragma unroll
    for (int jp = 0; jp < 2; jp++)
#pragma unroll
        for (int kk = 0; kk < 2; kk++)
            boff[jp][kk] = SWZ128((kk * 16 + kloc) * 128 + (nw + jp * 16 + noff) * 2);

    auto compute_stage = [&](int st) {
        const uint32_t bp = sb + st * DN_STAGE;
#pragma unroll
        for (int kk = 0; kk < 2; kk++) {
            uint32_t a[4][4];
            uint32_t bb[2][4];
#pragma unroll
            for (int jp = 0; jp < 2; jp++)
                ldsm_x4t(bb[jp][0], bb[jp][1], bb[jp][2], bb[jp][3], bp + DN_B + boff[jp][kk]);
#pragma unroll
            for (int i = 0; i < 4; i++)
                ldsm_x4(a[i][0], a[i][1], a[i][2], a[i][3], bp + DN_A + aoff[i][kk]);
#pragma unroll
            for (int i = 0; i < 4; i++)
#pragma unroll
                for (int jp = 0; jp < 2; jp++) {
                    mma_f16(acc[i][jp * 2 + 0], a[i], bb[jp][0], bb[jp][1]);
                    mma_f16(acc[i][jp * 2 + 1], a[i], bb[jp][2], bb[jp][3]);
                }
        }
    };

    const int NC = I / 32;
    load_stage(0, 0); CP_COMMIT();
    load_stage(1, 1); CP_COMMIT();
    for (int c = 0; c < NC; c += 2) {
        CP_WAIT0();
        __syncthreads();
        if (c + 2 < NC) { load_stage((c + 2) & 3, c + 2); CP_COMMIT(); }
        compute_stage(c & 3);
        if (c + 3 < NC) { load_stage((c + 3) & 3, c + 3); CP_COMMIT(); }
        compute_stage((c + 1) & 3);
    }

    const int r4 = lane >> 2;
    const int cp2 = (lane & 3) * 2;
#pragma unroll
    for (int i = 0; i < 4; i++)
#pragma unroll
        for (int hh = 0; hh < 2; hh++) {
            int row = mw + i * 16 + r4 + hh * 8;
            int slot = m0 + row;
            if (slot >= cnt) continue;
            int tok = tokSm[row];
            float w = wSm[row];
            float* dst = out + (size_t)tok * H;
#pragma unroll
            for (int j = 0; j < 4; j++) {
                int col = n0 + nw + (j >> 1) * 16 + (j & 1) * 8 + cp2;
                red_add_v2(dst + col, w * acc[i][j][hh * 2 + 0],
                                      w * acc[i][j][hh * 2 + 1]);
            }
        }
}

// ======================= launch =============================================
extern "C" void kernel_launch(void* const* d_in, const int* in_sizes, int n_in,
                              void* d_out, int out_size) {
    const float* x   = (const float*)d_in[0];
    const float* rw  = (const float*)d_in[1];
    const float* gw  = (const float*)d_in[2];
    const float* uw  = (const float*)d_in[3];
    const float* dw  = (const float*)d_in[4];
    const float* sgw = (const float*)d_in[5];
    const float* suw = (const float*)d_in[6];
    const float* sdw = (const float*)d_in[7];
    float* out = (float*)d_out;

    // one-time host-side resources (no device allocation)
    static bool s_init = false;
    static cudaStream_t s2;
    static cudaEvent_t evF, evGU, evD;
    if (!s_init) {
        cudaStreamCreateWithFlags(&s2, cudaStreamNonBlocking);
        cudaEventCreateWithFlags(&evF, cudaEventDisableTiming);
        cudaEventCreateWithFlags(&evGU, cudaEventDisableTiming);
        cudaEventCreateWithFlags(&evD, cudaEventDisableTiming);
        cudaFuncSetAttribute(mm_gateup_kernel,
                             cudaFuncAttributeMaxDynamicSharedMemorySize, GU_SMEM);
        cudaFuncSetAttribute(mm_down_kernel,
                             cudaFuncAttributeMaxDynamicSharedMemorySize, DN_SMEM);
        s_init = true;
    }

    init_kernel<<<1, 32>>>();

    // fork: weight conversions on s2, x/router on main (concurrent)
    cudaEventRecord(evF, 0);
    cudaStreamWaitEvent(s2, evF, 0);
    prep_w_gu_kernel<<<GUW_BLK, 256, 0, s2>>>(gw, uw, sgw, suw);
    cudaEventRecord(evGU, s2);
    prep_w_d_kernel<<<DW_BLK, 256, 0, s2>>>(dw, sdw);
    cudaEventRecord(evD, s2);

    prep_xr_kernel<<<T / 8, 256>>>(x, rw, out);
    finalize_kernel<<<1, 32>>>(out);

    // gateup needs g/u weights; down needs d weights (conv hidden under gateup)
    cudaStreamWaitEvent(0, evGU, 0);
    mm_gateup_kernel<<<dim3(I / 64, T / 128, E + 1), 256, GU_SMEM>>>();
    cudaStreamWaitEvent(0, evD, 0);
    mm_down_kernel<<<dim3(H / 64, T / 256, E + 1), 256, DN_SMEM>>>(out);
}

// round 15
// speedup vs baseline: 1.0177x; 1.0177x over previous
#include <cuda_runtime.h>
#include <cuda_fp16.h>
#include <math.h>
#include <stdint.h>

#define H 1024
#define I 2048
#define E 8
#define TOPK 2
#define T 4096   // B*S

// ======================= scratch (static device globals) =====================
__device__ __align__(256) int   g_counts[E];
__device__ __align__(256) float g_probsum[E];
__device__ float g_zsum;
__device__ __align__(256) int   g_list[E * T];
__device__ __align__(256) float g_wlist[E * T];

__device__ __align__(256) __half g_xh[(size_t)T * H];
__device__ __align__(256) __half g_g[(size_t)E * H * I];
__device__ __align__(256) __half g_u[(size_t)E * H * I];
__device__ __align__(256) __half g_d[(size_t)E * I * H];
__device__ __align__(256) __half g_sg[(size_t)H * I];
__device__ __align__(256) __half g_su[(size_t)H * I];
__device__ __align__(256) __half g_sd[(size_t)I * H];
__device__ __align__(256) __half g_acth[(size_t)(E + 1) * T * I];

// ======================= PTX helpers ========================================
static __device__ __forceinline__ uint32_t s2u(const void* p) {
    uint32_t a;
    asm("{ .reg .u64 t; cvta.to.shared.u64 t, %1; cvt.u32.u64 %0, t; }"
        : "=r"(a) : "l"(p));
    return a;
}
static __device__ __forceinline__ void ldsm_x4(uint32_t& r0, uint32_t& r1,
                                               uint32_t& r2, uint32_t& r3,
                                               uint32_t addr) {
    asm volatile("ldmatrix.sync.aligned.m8n8.x4.shared.b16 {%0,%1,%2,%3}, [%4];"
                 : "=r"(r0), "=r"(r1), "=r"(r2), "=r"(r3) : "r"(addr));
}
static __device__ __forceinline__ void ldsm_x4t(uint32_t& r0, uint32_t& r1,
                                                uint32_t& r2, uint32_t& r3,
                                                uint32_t addr) {
    asm volatile("ldmatrix.sync.aligned.m8n8.x4.trans.shared.b16 {%0,%1,%2,%3}, [%4];"
                 : "=r"(r0), "=r"(r1), "=r"(r2), "=r"(r3) : "r"(addr));
}
static __device__ __forceinline__ void mma_f16(float* c, const uint32_t* a,
                                               uint32_t b0, uint32_t b1) {
    asm volatile(
        "mma.sync.aligned.m16n8k16.row.col.f32.f16.f16.f32 "
        "{%0,%1,%2,%3}, {%4,%5,%6,%7}, {%8,%9}, {%0,%1,%2,%3};"
        : "+f"(c[0]), "+f"(c[1]), "+f"(c[2]), "+f"(c[3])
        : "r"(a[0]), "r"(a[1]), "r"(a[2]), "r"(a[3]), "r"(b0), "r"(b1));
}
static __device__ __forceinline__ void cp16(uint32_t dst, const void* src,
                                            uint32_t sz) {
    asm volatile("cp.async.cg.shared.global [%0], [%1], 16, %2;"
                 :: "r"(dst), "l"(src), "r"(sz) : "memory");
}
static __device__ __forceinline__ void red_add_v2(float* p, float v0, float v1) {
    asm volatile("red.global.add.v2.f32 [%0], {%1, %2};"
                 :: "l"(p), "f"(v0), "f"(v1) : "memory");
}
#define CP_COMMIT() asm volatile("cp.async.commit_group;" ::: "memory")
#define CP_WAIT0()  asm volatile("cp.async.wait_group 0;" ::: "memory")

#define SWZ64(o)  ((uint32_t)(o) ^ ((((uint32_t)(o)) >> 3) & 0x30u))
#define SWZ128(o) ((uint32_t)(o) ^ ((((uint32_t)(o)) >> 3) & 0x70u))

// ======================= SMEM layouts (per stage) ===========================
#define GU_A      0
#define GU_BG     8192
#define GU_BU     12288
#define GU_STAGE  16384
#define GU_SMEM   (1024 + 4 * GU_STAGE)
#define DN_A      0
#define DN_B      16384
#define DN_STAGE  20480
#define DN_SMEM   (2048 + 4 * DN_STAGE)

// ======================= init / finalize ====================================
__global__ void init_kernel() {
    int i = threadIdx.x;
    if (i < E) { g_counts[i] = 0; g_probsum[i] = 0.f; }
    if (i == 0) g_zsum = 0.f;
}

__global__ void finalize_kernel(float* __restrict__ out) {
    if (threadIdx.x == 0) {
        float aux = 0.f;
#pragma unroll
        for (int e = 0; e < E; e++) {
            float tpe = (float)g_counts[e] / (float)(TOPK * T);
            float ppe = g_probsum[e] / (float)T;
            aux += tpe * ppe;
        }
        out[(size_t)T * H]     = (float)E * aux;
        out[(size_t)T * H + 1] = g_zsum / (float)T;
    }
}

// ======================= weight conversion (MLP-batched) =====================
static __device__ __forceinline__ void round8(const float4 a, const float4 b,
                                              __half* dh, size_t o) {
    __half2 h0 = __floats2half2_rn(a.x, a.y);
    __half2 h1 = __floats2half2_rn(a.z, a.w);
    __half2 h2 = __floats2half2_rn(b.x, b.y);
    __half2 h3 = __floats2half2_rn(b.z, b.w);
    uint4 uh;
    uh.x = *(const uint32_t*)&h0; uh.y = *(const uint32_t*)&h1;
    uh.z = *(const uint32_t*)&h2; uh.w = *(const uint32_t*)&h3;
    *reinterpret_cast<uint4*>(dh + o) = uh;
}

#define GW8 ((size_t)E * H * I / 8)
#define SW8 ((size_t)H * I / 8)
#define GUW_PAIRS (2 * GW8 + 2 * SW8)
#define DW_PAIRS  (GW8 + SW8)
#define GUW_BLK (GUW_PAIRS / 512)
#define DW_BLK  (DW_PAIRS / 512)

__global__ void prep_w_gu_kernel(const float* __restrict__ gw,
                                 const float* __restrict__ uw,
                                 const float* __restrict__ sgw,
                                 const float* __restrict__ suw) {
    size_t pA = (size_t)blockIdx.x * 512 + threadIdx.x;
    size_t pB = pA + 256;
    const float *sA, *sB; __half *dA, *dB; size_t lA, lB;
    if (pA < GW8)            { sA = gw;  dA = g_g;  lA = pA; }
    else if (pA < 2 * GW8)   { sA = uw;  dA = g_u;  lA = pA - GW8; }
    else if (pA < 2 * GW8 + SW8) { sA = sgw; dA = g_sg; lA = pA - 2 * GW8; }
    else                     { sA = suw; dA = g_su; lA = pA - 2 * GW8 - SW8; }
    if (pB < GW8)            { sB = gw;  dB = g_g;  lB = pB; }
    else if (pB < 2 * GW8)   { sB = uw;  dB = g_u;  lB = pB - GW8; }
    else if (pB < 2 * GW8 + SW8) { sB = sgw; dB = g_sg; lB = pB - 2 * GW8; }
    else                     { sB = suw; dB = g_su; lB = pB - 2 * GW8 - SW8; }
    float4 a0 = reinterpret_cast<const float4*>(sA)[lA * 2];
    float4 a1 = reinterpret_cast<const float4*>(sA)[lA * 2 + 1];
    float4 b0 = reinterpret_cast<const float4*>(sB)[lB * 2];
    float4 b1 = reinterpret_cast<const float4*>(sB)[lB * 2 + 1];
    round8(a0, a1, dA, lA * 8);
    round8(b0, b1, dB, lB * 8);
}

__global__ void prep_w_d_kernel(const float* __restrict__ dw,
                                const float* __restrict__ sdw) {
    size_t pA = (size_t)blockIdx.x * 512 + threadIdx.x;
    size_t pB = pA + 256;
    const float *sA, *sB; __half *dA, *dB; size_t lA, lB;
    if (pA < GW8) { sA = dw;  dA = g_d;  lA = pA; }
    else          { sA = sdw; dA = g_sd; lA = pA - GW8; }
    if (pB < GW8) { sB = dw;  dB = g_d;  lB = pB; }
    else          { sB = sdw; dB = g_sd; lB = pB - GW8; }
    float4 a0 = reinterpret_cast<const float4*>(sA)[lA * 2];
    float4 a1 = reinterpret_cast<const float4*>(sA)[lA * 2 + 1];
    float4 b0 = reinterpret_cast<const float4*>(sB)[lB * 2];
    float4 b1 = reinterpret_cast<const float4*>(sB)[lB * 2 + 1];
    round8(a0, a1, dA, lA * 8);
    round8(b0, b1, dB, lB * 8);
}

// ======================= x-split + zero + router (SMEM rw) ===================
__global__ void prep_xr_kernel(const float* __restrict__ x,
                               const float* __restrict__ rw,
                               float* __restrict__ out) {
    __shared__ float s_rw[E][H];   // transposed router weights, 32 KB
    const int b = blockIdx.x;
    const int tid = threadIdx.x;

    // load rw [H][E] -> s_rw[E][H]
#pragma unroll
    for (int r = 0; r < (H * E) / 256; r++) {
        int i = tid + r * 256;
        int h = i >> 3, e = i & 7;
        s_rw[e][h] = rw[i];
    }

    // ---- x convert + zero (batched loads) ----
    {
        size_t base = (size_t)b * 1024;   // float4-pairs per block
        float4 v[8];
#pragma unroll
        for (int k = 0; k < 4; k++) {
            size_t p8 = base + tid + k * 256;
            v[2 * k]     = reinterpret_cast<const float4*>(x)[p8 * 2];
            v[2 * k + 1] = reinterpret_cast<const float4*>(x)[p8 * 2 + 1];
        }
        float4 z4 = make_float4(0.f, 0.f, 0.f, 0.f);
#pragma unroll
        for (int k = 0; k < 4; k++) {
            size_t p8 = base + tid + k * 256;
            round8(v[2 * k], v[2 * k + 1], g_xh, p8 * 8);
            reinterpret_cast<float4*>(out)[p8 * 2]     = z4;
            reinterpret_cast<float4*>(out)[p8 * 2 + 1] = z4;
        }
    }
    __syncthreads();

    // ---- router: 1 warp per token, float4 x + SMEM rw ----
    int t = b * 8 + (tid >> 5);
    int lane = tid & 31;
    const float* xr = x + (size_t)t * H;
    float* out_logits = out + (size_t)T * H + 2;

    float acc[E];
#pragma unroll
    for (int e = 0; e < E; e++) acc[e] = 0.f;
#pragma unroll
    for (int it = 0; it < H / 128; it++) {
        int h = lane * 4 + it * 128;
        float4 xv = *reinterpret_cast<const float4*>(xr + h);
#pragma unroll
        for (int e = 0; e < E; e++) {
            float4 rv = *reinterpret_cast<const float4*>(&s_rw[e][h]);
            acc[e] += xv.x * rv.x + xv.y * rv.y + xv.z * rv.z + xv.w * rv.w;
        }
    }
#pragma unroll
    for (int e = 0; e < E; e++)
#pragma unroll
        for (int off = 16; off > 0; off >>= 1)
            acc[e] += __shfl_xor_sync(0xffffffffu, acc[e], off);

    if (lane == 0) {
        float m = acc[0];
#pragma unroll
        for (int e = 1; e < E; e++) m = fmaxf(m, acc[e]);
        float p[E], s = 0.f;
#pragma unroll
        for (int e = 0; e < E; e++) { p[e] = expf(acc[e] - m); s += p[e]; }
        float inv = 1.f / s;
#pragma unroll
        for (int e = 0; e < E; e++) out_logits[(size_t)t * E + e] = acc[e];
        float lse = m + logf(s);
        atomicAdd(&g_zsum, lse * lse);
#pragma unroll
        for (int e = 0; e < E; e++) atomicAdd(&g_probsum[e], p[e] * inv);

        int e1 = 0;
#pragma unroll
        for (int e = 1; e < E; e++) if (acc[e] > acc[e1]) e1 = e;
        int e2 = (e1 == 0) ? 1 : 0;
#pragma unroll
        for (int e = 0; e < E; e++) if (e != e1 && acc[e] > acc[e2]) e2 = e;
        float p1 = p[e1] * inv, p2 = p[e2] * inv;
        float wn = 1.f / (p1 + p2);
        int pos1 = atomicAdd(&g_counts[e1], 1);
        g_list[e1 * T + pos1] = t;  g_wlist[e1 * T + pos1] = p1 * wn;
        int pos2 = atomicAdd(&g_counts[e2], 1);
        g_list[e2 * T + pos2] = t;  g_wlist[e2 * T + pos2] = p2 * wn;
    }
}

// ======================= GEMM 1: gate+up (plain fp16 HMMA) ===================
__global__ void __launch_bounds__(256, 2) mm_gateup_kernel() {
    extern __shared__ char smem[];
    const int e = blockIdx.z;
    const int cnt = (e < E) ? g_counts[e] : T;
    const int m0 = blockIdx.y * 128;
    if (m0 >= cnt) return;
    const int n0 = blockIdx.x * 64;
    const int tid = threadIdx.x;
    const int wid = tid >> 5;
    const int lane = tid & 31;

    int* rowTok = (int*)smem;
    if (tid < 128) {
        int slot = m0 + tid;
        rowTok[tid] = (slot < cnt) ? ((e < E) ? g_list[e * T + slot] : slot) : -1;
    }
    __syncthreads();

    const uint32_t sb = s2u(smem) + 1024;

    const __half* Gw = (e < E) ? g_g + (size_t)e * H * I : g_sg;
    const __half* Uw = (e < E) ? g_u + (size_t)e * H * I : g_su;

    const int u4 = tid & 3;
    const int rb = tid >> 2;
    const int tok0 = rowTok[rb];
    const int tok1 = rowTok[rb + 64];
    const size_t aG0 = (size_t)(tok0 >= 0 ? tok0 : 0) * H + u4 * 8;
    const size_t aG1 = (size_t)(tok1 >= 0 ? tok1 : 0) * H + u4 * 8;
    const uint32_t sz0 = (tok0 >= 0) ? 16u : 0u;
    const uint32_t sz1 = (tok1 >= 0) ? 16u : 0u;
    const uint32_t dA0 = SWZ64(rb * 64 + u4 * 16);
    const uint32_t dA1 = SWZ64((rb + 64) * 64 + u4 * 16);
    const int u8 = tid & 7;
    const int rbB = tid >> 3;
    const size_t bGsrc = (size_t)rbB * I + n0 + u8 * 8;
    const uint32_t dB = SWZ128(rbB * 128 + u8 * 16);

    auto load_stage = [&](int st, int c) {
        const int k0 = c * 32;
        const uint32_t bp = sb + st * GU_STAGE;
        cp16(bp + GU_A + dA0, g_xh + aG0 + k0, sz0);
        cp16(bp + GU_A + dA1, g_xh + aG1 + k0, sz1);
        size_t bo = bGsrc + (size_t)k0 * I;
        cp16(bp + GU_BG + dB, Gw + bo, 16);
        cp16(bp + GU_BU + dB, Uw + bo, 16);
    };

    float accG[2][4][4], accU[2][4][4];
#pragma unroll
    for (int i = 0; i < 2; i++)
#pragma unroll
        for (int j = 0; j < 4; j++)
#pragma unroll
            for (int q = 0; q < 4; q++) { accG[i][j][q] = 0.f; accU[i][j][q] = 0.f; }

    const int mw = (wid >> 1) * 32;
    const int nw = (wid & 1) * 32;
    const int arow_off = ((lane >> 3) & 1) * 8 + (lane & 7);
    const int akb_off = (lane >> 4) * 16;
    const int kloc = (lane & 7) + ((lane >> 3) & 1) * 8;
    const int noff = (lane >> 4) * 8;

    uint32_t aoff[2][2], boff[2][2];
#pragma unroll
    for (int i = 0; i < 2; i++)
#pragma unroll
        for (int kk = 0; kk < 2; kk++)
            aoff[i][kk] = SWZ64((mw + i * 16 + arow_off) * 64 + kk * 32 + akb_off);
#pragma unroll
    for (int jp = 0; jp < 2; jp++)
#pragma unroll
        for (int kk = 0; kk < 2; kk++)
            boff[jp][kk] = SWZ128((kk * 16 + kloc) * 128 + (nw + jp * 16 + noff) * 2);

    auto compute_stage = [&](int st) {
        const uint32_t bp = sb + st * GU_STAGE;
#pragma unroll
        for (int kk = 0; kk < 2; kk++) {
            uint32_t a[2][4];
            uint32_t gb[2][4], ub[2][4];
#pragma unroll
            for (int jp = 0; jp < 2; jp++) {
                ldsm_x4t(gb[jp][0], gb[jp][1], gb[jp][2], gb[jp][3], bp + GU_BG + boff[jp][kk]);
                ldsm_x4t(ub[jp][0], ub[jp][1], ub[jp][2], ub[jp][3], bp + GU_BU + boff[jp][kk]);
            }
#pragma unroll
            for (int i = 0; i < 2; i++)
                ldsm_x4(a[i][0], a[i][1], a[i][2], a[i][3], bp + GU_A + aoff[i][kk]);
#pragma unroll
            for (int i = 0; i < 2; i++)
#pragma unroll
                for (int jp = 0; jp < 2; jp++) {
                    mma_f16(accG[i][jp * 2 + 0], a[i], gb[jp][0], gb[jp][1]);
                    mma_f16(accG[i][jp * 2 + 1], a[i], gb[jp][2], gb[jp][3]);
                    mma_f16(accU[i][jp * 2 + 0], a[i], ub[jp][0], ub[jp][1]);
                    mma_f16(accU[i][jp * 2 + 1], a[i], ub[jp][2], ub[jp][3]);
                }
        }
    };

    const int NC = H / 32;  // 32 chunks, 16 pairs
    load_stage(0, 0); CP_COMMIT();
    load_stage(1, 1); CP_COMMIT();
    for (int c = 0; c < NC; c += 2) {
        CP_WAIT0();
        __syncthreads();
        if (c + 2 < NC) { load_stage((c + 2) & 3, c + 2); CP_COMMIT(); }
        compute_stage(c & 3);
        if (c + 3 < NC) { load_stage((c + 3) & 3, c + 3); CP_COMMIT(); }
        compute_stage((c + 1) & 3);
    }

    const int r4 = lane >> 2;
    const int cp2 = (lane & 3) * 2;
#pragma unroll
    for (int i = 0; i < 2; i++)
#pragma unroll
        for (int hh = 0; hh < 2; hh++) {
            int slot = m0 + mw + i * 16 + r4 + hh * 8;
            if (slot >= cnt) continue;
#pragma unroll
            for (int j = 0; j < 4; j++) {
                float g0 = accG[i][j][hh * 2 + 0], g1 = accG[i][j][hh * 2 + 1];
                float u0 = accU[i][j][hh * 2 + 0], u1 = accU[i][j][hh * 2 + 1];
                float v0 = g0 / (1.f + __expf(-g0)) * u0;
                float v1 = g1 / (1.f + __expf(-g1)) * u1;
                __half2 hp;
                hp.x = __float2half(v0); hp.y = __float2half(v1);
                int coln = nw + (j >> 1) * 16 + (j & 1) * 8 + cp2;
                size_t ai = (size_t)e * T * I + (size_t)slot * I + n0 + coln;
                *reinterpret_cast<__half2*>(g_acth + ai) = hp;
            }
        }
}

// ======================= GEMM 2: down (fused, M=256, warp 64x32) =============
__global__ void __launch_bounds__(256, 2) mm_down_kernel(float* __restrict__ out) {
    extern __shared__ char smem[];
    const int ez = blockIdx.z;
    const bool routed = (ez < E);
    const int cnt = routed ? g_counts[ez] : T;
    const int m0 = blockIdx.y * 256;
    if (m0 >= cnt) return;
    const int n0 = blockIdx.x * 64;
    const int tid = threadIdx.x;
    const int wid = tid >> 5;
    const int lane = tid & 31;

    int* tokSm = (int*)smem;
    float* wSm = (float*)(smem + 1024);
    {
        int slot = m0 + tid;
        if (routed) {
            tokSm[tid] = (slot < cnt) ? g_list[ez * T + slot] : 0;
            wSm[tid]   = (slot < cnt) ? g_wlist[ez * T + slot] : 0.f;
        } else {
            tokSm[tid] = slot;
            wSm[tid]   = 1.f;
        }
    }
    __syncthreads();

    const uint32_t sb = s2u(smem) + 2048;

    const __half* Bw = routed ? g_d + (size_t)ez * I * H : g_sd;
    const __half* Ah = g_acth + (size_t)ez * T * I;

    const int u4 = tid & 3;
    const int rb = tid >> 2;
    size_t aO[4];
    uint32_t szA[4], dA[4];
#pragma unroll
    for (int r = 0; r < 4; r++) {
        int row = rb + r * 64;
        int slot = m0 + row;
        aO[r]  = (size_t)(slot < cnt ? slot : 0) * I + u4 * 8;
        szA[r] = (slot < cnt) ? 16u : 0u;
        dA[r]  = SWZ64(row * 64 + u4 * 16);
    }
    const int u8 = tid & 7;
    const int rbB = tid >> 3;
    const size_t bSrc = (size_t)rbB * H + n0 + u8 * 8;
    const uint32_t dB = SWZ128(rbB * 128 + u8 * 16);

    auto load_stage = [&](int st, int c) {
        const int k0 = c * 32;
        const uint32_t bp = sb + st * DN_STAGE;
#pragma unroll
        for (int r = 0; r < 4; r++)
            cp16(bp + DN_A + dA[r], Ah + aO[r] + k0, szA[r]);
        size_t bo = bSrc + (size_t)k0 * H;
        cp16(bp + DN_B + dB, Bw + bo, 16);
    };

    float acc[4][4][4];
#pragma unroll
    for (int i = 0; i < 4; i++)
#pragma unroll
        for (int j = 0; j < 4; j++)
#pragma unroll
            for (int q = 0; q < 4; q++) acc[i][j][q] = 0.f;

    const int mw = (wid >> 1) * 64;
    const int nw = (wid & 1) * 32;
    const int arow_off = ((lane >> 3) & 1) * 8 + (lane & 7);
    const int akb_off = (lane >> 4) * 16;
    const int kloc = (lane & 7) + ((lane >> 3) & 1) * 8;
    const int noff = (lane >> 4) * 8;

    uint32_t aoff[4][2], boff[2][2];
#pragma unroll
    for (int i = 0; i < 4; i++)
#pragma unroll
        for (int kk = 0; kk < 2; kk++)
            aoff[i][kk] = SWZ64((mw + i * 16 + arow_off) * 64 + kk * 32 + akb_off);
#pragma unroll
    for (int jp = 0; jp < 2; jp++)
#pragma unroll
        for (int kk = 0; kk < 2; kk++)
            boff[jp][kk] = SWZ128((kk * 16 + kloc) * 128 + (nw + jp * 16 + noff) * 2);

    auto compute_stage = [&](int st) {
        const uint32_t bp = sb + st * DN_STAGE;
#pragma unroll
        for (int kk = 0; kk < 2; kk++) {
            uint32_t a[4][4];
            uint32_t bb[2][4];
#pragma unroll
            for (int jp = 0; jp < 2; jp++)
                ldsm_x4t(bb[jp][0], bb[jp][1], bb[jp][2], bb[jp][3], bp + DN_B + boff[jp][kk]);
#pragma unroll
            for (int i = 0; i < 4; i++)
                ldsm_x4(a[i][0], a[i][1], a[i][2], a[i][3], bp + DN_A + aoff[i][kk]);
#pragma unroll
            for (int i = 0; i < 4; i++)
#pragma unroll
                for (int jp = 0; jp < 2; jp++) {
                    mma_f16(acc[i][jp * 2 + 0], a[i], bb[jp][0], bb[jp][1]);
                    mma_f16(acc[i][jp * 2 + 1], a[i], bb[jp][2], bb[jp][3]);
                }
        }
    };

    const int NC = I / 32;
    load_stage(0, 0); CP_COMMIT();
    load_stage(1, 1); CP_COMMIT();
    for (int c = 0; c < NC; c += 2) {
        CP_WAIT0();
        __syncthreads();
        if (c + 2 < NC) { load_stage((c + 2) & 3, c + 2); CP_COMMIT(); }
        compute_stage(c & 3);
        if (c + 3 < NC) { load_stage((c + 3) & 3, c + 3); CP_COMMIT(); }
        compute_stage((c + 1) & 3);
    }

    const int r4 = lane >> 2;
    const int cp2 = (lane & 3) * 2;
#pragma unroll
    for (int i = 0; i < 4; i++)
#pragma unroll
        for (int hh = 0; hh < 2; hh++) {
            int row = mw + i * 16 + r4 + hh * 8;
            int slot = m0 + row;
            if (slot >= cnt) continue;
            int tok = tokSm[row];
            float w = wSm[row];
            float* dst = out + (size_t)tok * H;
#pragma unroll
            for (int j = 0; j < 4; j++) {
                int col = n0 + nw + (j >> 1) * 16 + (j & 1) * 8 + cp2;
                red_add_v2(dst + col, w * acc[i][j][hh * 2 + 0],
                                      w * acc[i][j][hh * 2 + 1]);
            }
        }
}

// ======================= launch =============================================
extern "C" void kernel_launch(void* const* d_in, const int* in_sizes, int n_in,
                              void* d_out, int out_size) {
    const float* x   = (const float*)d_in[0];
    const float* rw  = (const float*)d_in[1];
    const float* gw  = (const float*)d_in[2];
    const float* uw  = (const float*)d_in[3];
    const float* dw  = (const float*)d_in[4];
    const float* sgw = (const float*)d_in[5];
    const float* suw = (const float*)d_in[6];
    const float* sdw = (const float*)d_in[7];
    float* out = (float*)d_out;

    static bool s_init = false;
    static cudaStream_t s2;
    static cudaEvent_t evF, evGU, evD;
    if (!s_init) {
        cudaStreamCreateWithFlags(&s2, cudaStreamNonBlocking);
        cudaEventCreateWithFlags(&evF, cudaEventDisableTiming);
        cudaEventCreateWithFlags(&evGU, cudaEventDisableTiming);
        cudaEventCreateWithFlags(&evD, cudaEventDisableTiming);
        cudaFuncSetAttribute(mm_gateup_kernel,
                             cudaFuncAttributeMaxDynamicSharedMemorySize, GU_SMEM);
        cudaFuncSetAttribute(mm_down_kernel,
                             cudaFuncAttributeMaxDynamicSharedMemorySize, DN_SMEM);
        s_init = true;
    }

    init_kernel<<<1, 32>>>();

    // fork: weight conversions on s2, x/router on main (concurrent)
    cudaEventRecord(evF, 0);
    cudaStreamWaitEvent(s2, evF, 0);
    prep_w_gu_kernel<<<GUW_BLK, 256, 0, s2>>>(gw, uw, sgw, suw);
    cudaEventRecord(evGU, s2);
    prep_w_d_kernel<<<DW_BLK, 256, 0, s2>>>(dw, sdw);
    cudaEventRecord(evD, s2);

    prep_xr_kernel<<<T / 8, 256>>>(x, rw, out);
    finalize_kernel<<<1, 32>>>(out);

    cudaStreamWaitEvent(0, evGU, 0);
    mm_gateup_kernel<<<dim3(I / 64, T / 128, E + 1), 256, GU_SMEM>>>();
    cudaStreamWaitEvent(0, evD, 0);
    mm_down_kernel<<<dim3(H / 64, T / 256, E + 1), 256, DN_SMEM>>>(out);
}

// round 16
// speedup vs baseline: 1.0954x; 1.0763x over previous
#include <cuda_runtime.h>
#include <cuda_fp16.h>
#include <math.h>
#include <stdint.h>

#define H 1024
#define I 2048
#define E 8
#define TOPK 2
#define T 4096   // B*S

// ======================= scratch (static device globals) =====================
__device__ __align__(256) int   g_counts[E];
__device__ __align__(256) float g_probsum[E];
__device__ float g_zsum;
__device__ __align__(256) int   g_list[E * T];
__device__ __align__(256) float g_wlist[E * T];

__device__ __align__(256) __half g_xh[(size_t)T * H];
__device__ __align__(256) __half g_g[(size_t)E * H * I];
__device__ __align__(256) __half g_u[(size_t)E * H * I];
__device__ __align__(256) __half g_d[(size_t)E * I * H];
__device__ __align__(256) __half g_sg[(size_t)H * I];
__device__ __align__(256) __half g_su[(size_t)H * I];
__device__ __align__(256) __half g_sd[(size_t)I * H];
__device__ __align__(256) __half g_acth[(size_t)(E + 1) * T * I];

// ======================= PTX helpers ========================================
static __device__ __forceinline__ uint32_t s2u(const void* p) {
    uint32_t a;
    asm("{ .reg .u64 t; cvta.to.shared.u64 t, %1; cvt.u32.u64 %0, t; }"
        : "=r"(a) : "l"(p));
    return a;
}
static __device__ __forceinline__ void ldsm_x4(uint32_t& r0, uint32_t& r1,
                                               uint32_t& r2, uint32_t& r3,
                                               uint32_t addr) {
    asm volatile("ldmatrix.sync.aligned.m8n8.x4.shared.b16 {%0,%1,%2,%3}, [%4];"
                 : "=r"(r0), "=r"(r1), "=r"(r2), "=r"(r3) : "r"(addr));
}
static __device__ __forceinline__ void ldsm_x4t(uint32_t& r0, uint32_t& r1,
                                                uint32_t& r2, uint32_t& r3,
                                                uint32_t addr) {
    asm volatile("ldmatrix.sync.aligned.m8n8.x4.trans.shared.b16 {%0,%1,%2,%3}, [%4];"
                 : "=r"(r0), "=r"(r1), "=r"(r2), "=r"(r3) : "r"(addr));
}
static __device__ __forceinline__ void mma_f16(float* c, const uint32_t* a,
                                               uint32_t b0, uint32_t b1) {
    asm volatile(
        "mma.sync.aligned.m16n8k16.row.col.f32.f16.f16.f32 "
        "{%0,%1,%2,%3}, {%4,%5,%6,%7}, {%8,%9}, {%0,%1,%2,%3};"
        : "+f"(c[0]), "+f"(c[1]), "+f"(c[2]), "+f"(c[3])
        : "r"(a[0]), "r"(a[1]), "r"(a[2]), "r"(a[3]), "r"(b0), "r"(b1));
}
static __device__ __forceinline__ void cp16(uint32_t dst, const void* src,
                                            uint32_t sz) {
    asm volatile("cp.async.cg.shared.global [%0], [%1], 16, %2;"
                 :: "r"(dst), "l"(src), "r"(sz) : "memory");
}
static __device__ __forceinline__ void red_add_v2(float* p, float v0, float v1) {
    asm volatile("red.global.add.v2.f32 [%0], {%1, %2};"
                 :: "l"(p), "f"(v0), "f"(v1) : "memory");
}
#define CP_COMMIT() asm volatile("cp.async.commit_group;" ::: "memory")
#define CP_WAIT0()  asm volatile("cp.async.wait_group 0;" ::: "memory")

#define SWZ64(o)  ((uint32_t)(o) ^ ((((uint32_t)(o)) >> 3) & 0x30u))
#define SWZ128(o) ((uint32_t)(o) ^ ((((uint32_t)(o)) >> 3) & 0x70u))

// ======================= SMEM layouts (per stage) ===========================
#define GU_A      0
#define GU_BG     8192
#define GU_BU     12288
#define GU_STAGE  16384
#define GU_SMEM   (1024 + 4 * GU_STAGE)
#define DN_A      0
#define DN_B      16384
#define DN_STAGE  20480
#define DN_SMEM   (2048 + 4 * DN_STAGE)

// ======================= init / finalize ====================================
__global__ void init_kernel() {
    int i = threadIdx.x;
    if (i < E) { g_counts[i] = 0; g_probsum[i] = 0.f; }
    if (i == 0) g_zsum = 0.f;
}

__global__ void finalize_kernel(float* __restrict__ out) {
    if (threadIdx.x == 0) {
        float aux = 0.f;
#pragma unroll
        for (int e = 0; e < E; e++) {
            float tpe = (float)g_counts[e] / (float)(TOPK * T);
            float ppe = g_probsum[e] / (float)T;
            aux += tpe * ppe;
        }
        out[(size_t)T * H]     = (float)E * aux;
        out[(size_t)T * H + 1] = g_zsum / (float)T;
    }
}

// ======================= conversions ========================================
static __device__ __forceinline__ void round8(const float4 a, const float4 b,
                                              __half* dh, size_t o) {
    __half2 h0 = __floats2half2_rn(a.x, a.y);
    __half2 h1 = __floats2half2_rn(a.z, a.w);
    __half2 h2 = __floats2half2_rn(b.x, b.y);
    __half2 h3 = __floats2half2_rn(b.z, b.w);
    uint4 uh;
    uh.x = *(const uint32_t*)&h0; uh.y = *(const uint32_t*)&h1;
    uh.z = *(const uint32_t*)&h2; uh.w = *(const uint32_t*)&h3;
    *reinterpret_cast<uint4*>(dh + o) = uh;
}

#define GW8 ((size_t)E * H * I / 8)
#define SW8 ((size_t)H * I / 8)
#define GUW_PAIRS (2 * GW8 + 2 * SW8)
#define DW_PAIRS  (GW8 + SW8)
#define GUW_BLK (GUW_PAIRS / 512)
#define DW_BLK  (DW_PAIRS / 512)

__global__ void prep_w_gu_kernel(const float* __restrict__ gw,
                                 const float* __restrict__ uw,
                                 const float* __restrict__ sgw,
                                 const float* __restrict__ suw) {
    size_t pA = (size_t)blockIdx.x * 512 + threadIdx.x;
    size_t pB = pA + 256;
    const float *sA, *sB; __half *dA, *dB; size_t lA, lB;
    if (pA < GW8)            { sA = gw;  dA = g_g;  lA = pA; }
    else if (pA < 2 * GW8)   { sA = uw;  dA = g_u;  lA = pA - GW8; }
    else if (pA < 2 * GW8 + SW8) { sA = sgw; dA = g_sg; lA = pA - 2 * GW8; }
    else                     { sA = suw; dA = g_su; lA = pA - 2 * GW8 - SW8; }
    if (pB < GW8)            { sB = gw;  dB = g_g;  lB = pB; }
    else if (pB < 2 * GW8)   { sB = uw;  dB = g_u;  lB = pB - GW8; }
    else if (pB < 2 * GW8 + SW8) { sB = sgw; dB = g_sg; lB = pB - 2 * GW8; }
    else                     { sB = suw; dB = g_su; lB = pB - 2 * GW8 - SW8; }
    float4 a0 = reinterpret_cast<const float4*>(sA)[lA * 2];
    float4 a1 = reinterpret_cast<const float4*>(sA)[lA * 2 + 1];
    float4 b0 = reinterpret_cast<const float4*>(sB)[lB * 2];
    float4 b1 = reinterpret_cast<const float4*>(sB)[lB * 2 + 1];
    round8(a0, a1, dA, lA * 8);
    round8(b0, b1, dB, lB * 8);
}

__global__ void prep_w_d_kernel(const float* __restrict__ dw,
                                const float* __restrict__ sdw) {
    size_t pA = (size_t)blockIdx.x * 512 + threadIdx.x;
    size_t pB = pA + 256;
    const float *sA, *sB; __half *dA, *dB; size_t lA, lB;
    if (pA < GW8) { sA = dw;  dA = g_d;  lA = pA; }
    else          { sA = sdw; dA = g_sd; lA = pA - GW8; }
    if (pB < GW8) { sB = dw;  dB = g_d;  lB = pB; }
    else          { sB = sdw; dB = g_sd; lB = pB - GW8; }
    float4 a0 = reinterpret_cast<const float4*>(sA)[lA * 2];
    float4 a1 = reinterpret_cast<const float4*>(sA)[lA * 2 + 1];
    float4 b0 = reinterpret_cast<const float4*>(sB)[lB * 2];
    float4 b1 = reinterpret_cast<const float4*>(sB)[lB * 2 + 1];
    round8(a0, a1, dA, lA * 8);
    round8(b0, b1, dB, lB * 8);
}

// x -> fp16 (pure streaming, 1024 blocks, 4 loads in flight)
__global__ void xconv_kernel(const float* __restrict__ x) {
    size_t p = (size_t)blockIdx.x * 512 + threadIdx.x;   // pair index
    size_t q = p + 256;
    float4 a0 = reinterpret_cast<const float4*>(x)[p * 2];
    float4 a1 = reinterpret_cast<const float4*>(x)[p * 2 + 1];
    float4 b0 = reinterpret_cast<const float4*>(x)[q * 2];
    float4 b1 = reinterpret_cast<const float4*>(x)[q * 2 + 1];
    round8(a0, a1, g_xh, p * 8);
    round8(b0, b1, g_xh, q * 8);
}

// ======================= router (block-aggregated atomics) ===================
__global__ void router_kernel(const float* __restrict__ x,
                              const float* __restrict__ rw,
                              float* __restrict__ out) {
    __shared__ float s_rw[E][H];     // 32 KB
    __shared__ float s_p[8][E];
    __shared__ float s_z[8];
    const int b = blockIdx.x;
    const int tid = threadIdx.x;

#pragma unroll
    for (int r = 0; r < (H * E) / 256; r++) {
        int i = tid + r * 256;
        s_rw[i & 7][i >> 3] = rw[i];
    }
    __syncthreads();

    int t = b * 8 + (tid >> 5);
    int lane = tid & 31;
    int w = tid >> 5;
    const float* xr = x + (size_t)t * H;
    float* out_logits = out + (size_t)T * H + 2;

    float acc[E];
#pragma unroll
    for (int e = 0; e < E; e++) acc[e] = 0.f;
#pragma unroll
    for (int it = 0; it < H / 128; it++) {
        int h = lane * 4 + it * 128;
        float4 xv = *reinterpret_cast<const float4*>(xr + h);
#pragma unroll
        for (int e = 0; e < E; e++) {
            float4 rv = *reinterpret_cast<const float4*>(&s_rw[e][h]);
            acc[e] += xv.x * rv.x + xv.y * rv.y + xv.z * rv.z + xv.w * rv.w;
        }
    }
#pragma unroll
    for (int e = 0; e < E; e++)
#pragma unroll
        for (int off = 16; off > 0; off >>= 1)
            acc[e] += __shfl_xor_sync(0xffffffffu, acc[e], off);

    if (lane == 0) {
        float m = acc[0];
#pragma unroll
        for (int e = 1; e < E; e++) m = fmaxf(m, acc[e]);
        float p[E], s = 0.f;
#pragma unroll
        for (int e = 0; e < E; e++) { p[e] = expf(acc[e] - m); s += p[e]; }
        float inv = 1.f / s;
#pragma unroll
        for (int e = 0; e < E; e++) {
            out_logits[(size_t)t * E + e] = acc[e];
            s_p[w][e] = p[e] * inv;
        }
        float lse = m + logf(s);
        s_z[w] = lse * lse;

        int e1 = 0;
#pragma unroll
        for (int e = 1; e < E; e++) if (acc[e] > acc[e1]) e1 = e;
        int e2 = (e1 == 0) ? 1 : 0;
#pragma unroll
        for (int e = 0; e < E; e++) if (e != e1 && acc[e] > acc[e2]) e2 = e;
        float p1 = p[e1] * inv, p2 = p[e2] * inv;
        float wn = 1.f / (p1 + p2);
        int pos1 = atomicAdd(&g_counts[e1], 1);
        g_list[e1 * T + pos1] = t;  g_wlist[e1 * T + pos1] = p1 * wn;
        int pos2 = atomicAdd(&g_counts[e2], 1);
        g_list[e2 * T + pos2] = t;  g_wlist[e2 * T + pos2] = p2 * wn;
    }
    __syncthreads();
    // one atomic per expert per block (+1 for zsum)
    if (tid < E) {
        float sum = 0.f;
#pragma unroll
        for (int k = 0; k < 8; k++) sum += s_p[k][tid];
        atomicAdd(&g_probsum[tid], sum);
    } else if (tid == E) {
        float sum = 0.f;
#pragma unroll
        for (int k = 0; k < 8; k++) sum += s_z[k];
        atomicAdd(&g_zsum, sum);
    }
}

// ======================= GEMM 1: gate+up (plain fp16 HMMA) ===================
__global__ void __launch_bounds__(256, 2) mm_gateup_kernel() {
    extern __shared__ char smem[];
    const int e = blockIdx.z;
    const int cnt = (e < E) ? g_counts[e] : T;
    const int m0 = blockIdx.y * 128;
    if (m0 >= cnt) return;
    const int n0 = blockIdx.x * 64;
    const int tid = threadIdx.x;
    const int wid = tid >> 5;
    const int lane = tid & 31;

    int* rowTok = (int*)smem;
    if (tid < 128) {
        int slot = m0 + tid;
        rowTok[tid] = (slot < cnt) ? ((e < E) ? g_list[e * T + slot] : slot) : -1;
    }
    __syncthreads();

    const uint32_t sb = s2u(smem) + 1024;

    const __half* Gw = (e < E) ? g_g + (size_t)e * H * I : g_sg;
    const __half* Uw = (e < E) ? g_u + (size_t)e * H * I : g_su;

    const int u4 = tid & 3;
    const int rb = tid >> 2;
    const int tok0 = rowTok[rb];
    const int tok1 = rowTok[rb + 64];
    const size_t aG0 = (size_t)(tok0 >= 0 ? tok0 : 0) * H + u4 * 8;
    const size_t aG1 = (size_t)(tok1 >= 0 ? tok1 : 0) * H + u4 * 8;
    const uint32_t sz0 = (tok0 >= 0) ? 16u : 0u;
    const uint32_t sz1 = (tok1 >= 0) ? 16u : 0u;
    const uint32_t dA0 = SWZ64(rb * 64 + u4 * 16);
    const uint32_t dA1 = SWZ64((rb + 64) * 64 + u4 * 16);
    const int u8 = tid & 7;
    const int rbB = tid >> 3;
    const size_t bGsrc = (size_t)rbB * I + n0 + u8 * 8;
    const uint32_t dB = SWZ128(rbB * 128 + u8 * 16);

    auto load_stage = [&](int st, int c) {
        const int k0 = c * 32;
        const uint32_t bp = sb + st * GU_STAGE;
        cp16(bp + GU_A + dA0, g_xh + aG0 + k0, sz0);
        cp16(bp + GU_A + dA1, g_xh + aG1 + k0, sz1);
        size_t bo = bGsrc + (size_t)k0 * I;
        cp16(bp + GU_BG + dB, Gw + bo, 16);
        cp16(bp + GU_BU + dB, Uw + bo, 16);
    };

    float accG[2][4][4], accU[2][4][4];
#pragma unroll
    for (int i = 0; i < 2; i++)
#pragma unroll
        for (int j = 0; j < 4; j++)
#pragma unroll
            for (int q = 0; q < 4; q++) { accG[i][j][q] = 0.f; accU[i][j][q] = 0.f; }

    const int mw = (wid >> 1) * 32;
    const int nw = (wid & 1) * 32;
    const int arow_off = ((lane >> 3) & 1) * 8 + (lane & 7);
    const int akb_off = (lane >> 4) * 16;
    const int kloc = (lane & 7) + ((lane >> 3) & 1) * 8;
    const int noff = (lane >> 4) * 8;

    uint32_t aoff[2][2], boff[2][2];
#pragma unroll
    for (int i = 0; i < 2; i++)
#pragma unroll
        for (int kk = 0; kk < 2; kk++)
            aoff[i][kk] = SWZ64((mw + i * 16 + arow_off) * 64 + kk * 32 + akb_off);
#pragma unroll
    for (int jp = 0; jp < 2; jp++)
#pragma unroll
        for (int kk = 0; kk < 2; kk++)
            boff[jp][kk] = SWZ128((kk * 16 + kloc) * 128 + (nw + jp * 16 + noff) * 2);

    auto compute_stage = [&](int st) {
        const uint32_t bp = sb + st * GU_STAGE;
#pragma unroll
        for (int kk = 0; kk < 2; kk++) {
            uint32_t a[2][4];
            uint32_t gb[2][4], ub[2][4];
#pragma unroll
            for (int jp = 0; jp < 2; jp++) {
                ldsm_x4t(gb[jp][0], gb[jp][1], gb[jp][2], gb[jp][3], bp + GU_BG + boff[jp][kk]);
                ldsm_x4t(ub[jp][0], ub[jp][1], ub[jp][2], ub[jp][3], bp + GU_BU + boff[jp][kk]);
            }
#pragma unroll
            for (int i = 0; i < 2; i++)
                ldsm_x4(a[i][0], a[i][1], a[i][2], a[i][3], bp + GU_A + aoff[i][kk]);
#pragma unroll
            for (int i = 0; i < 2; i++)
#pragma unroll
                for (int jp = 0; jp < 2; jp++) {
                    mma_f16(accG[i][jp * 2 + 0], a[i], gb[jp][0], gb[jp][1]);
                    mma_f16(accG[i][jp * 2 + 1], a[i], gb[jp][2], gb[jp][3]);
                    mma_f16(accU[i][jp * 2 + 0], a[i], ub[jp][0], ub[jp][1]);
                    mma_f16(accU[i][jp * 2 + 1], a[i], ub[jp][2], ub[jp][3]);
                }
        }
    };

    const int NC = H / 32;  // 32 chunks, 16 pairs
    load_stage(0, 0); CP_COMMIT();
    load_stage(1, 1); CP_COMMIT();
    for (int c = 0; c < NC; c += 2) {
        CP_WAIT0();
        __syncthreads();
        if (c + 2 < NC) { load_stage((c + 2) & 3, c + 2); CP_COMMIT(); }
        compute_stage(c & 3);
        if (c + 3 < NC) { load_stage((c + 3) & 3, c + 3); CP_COMMIT(); }
        compute_stage((c + 1) & 3);
    }

    const int r4 = lane >> 2;
    const int cp2 = (lane & 3) * 2;
#pragma unroll
    for (int i = 0; i < 2; i++)
#pragma unroll
        for (int hh = 0; hh < 2; hh++) {
            int slot = m0 + mw + i * 16 + r4 + hh * 8;
            if (slot >= cnt) continue;
#pragma unroll
            for (int j = 0; j < 4; j++) {
                float g0 = accG[i][j][hh * 2 + 0], g1 = accG[i][j][hh * 2 + 1];
                float u0 = accU[i][j][hh * 2 + 0], u1 = accU[i][j][hh * 2 + 1];
                float v0 = g0 / (1.f + __expf(-g0)) * u0;
                float v1 = g1 / (1.f + __expf(-g1)) * u1;
                __half2 hp;
                hp.x = __float2half(v0); hp.y = __float2half(v1);
                int coln = nw + (j >> 1) * 16 + (j & 1) * 8 + cp2;
                size_t ai = (size_t)e * T * I + (size_t)slot * I + n0 + coln;
                *reinterpret_cast<__half2*>(g_acth + ai) = hp;
            }
        }
}

// ======================= GEMM 2: down (fused, M=256, warp 64x32) =============
__global__ void __launch_bounds__(256, 2) mm_down_kernel(float* __restrict__ out) {
    extern __shared__ char smem[];
    const int ez = blockIdx.z;
    const bool routed = (ez < E);
    const int cnt = routed ? g_counts[ez] : T;
    const int m0 = blockIdx.y * 256;
    if (m0 >= cnt) return;
    const int n0 = blockIdx.x * 64;
    const int tid = threadIdx.x;
    const int wid = tid >> 5;
    const int lane = tid & 31;

    int* tokSm = (int*)smem;
    float* wSm = (float*)(smem + 1024);
    {
        int slot = m0 + tid;
        if (routed) {
            tokSm[tid] = (slot < cnt) ? g_list[ez * T + slot] : 0;
            wSm[tid]   = (slot < cnt) ? g_wlist[ez * T + slot] : 0.f;
        } else {
            tokSm[tid] = slot;
            wSm[tid]   = 1.f;
        }
    }
    __syncthreads();

    const uint32_t sb = s2u(smem) + 2048;

    const __half* Bw = routed ? g_d + (size_t)ez * I * H : g_sd;
    const __half* Ah = g_acth + (size_t)ez * T * I;

    const int u4 = tid & 3;
    const int rb = tid >> 2;
    size_t aO[4];
    uint32_t szA[4], dA[4];
#pragma unroll
    for (int r = 0; r < 4; r++) {
        int row = rb + r * 64;
        int slot = m0 + row;
        aO[r]  = (size_t)(slot < cnt ? slot : 0) * I + u4 * 8;
        szA[r] = (slot < cnt) ? 16u : 0u;
        dA[r]  = SWZ64(row * 64 + u4 * 16);
    }
    const int u8 = tid & 7;
    const int rbB = tid >> 3;
    const size_t bSrc = (size_t)rbB * H + n0 + u8 * 8;
    const uint32_t dB = SWZ128(rbB * 128 + u8 * 16);

    auto load_stage = [&](int st, int c) {
        const int k0 = c * 32;
        const uint32_t bp = sb + st * DN_STAGE;
#pragma unroll
        for (int r = 0; r < 4; r++)
            cp16(bp + DN_A + dA[r], Ah + aO[r] + k0, szA[r]);
        size_t bo = bSrc + (size_t)k0 * H;
        cp16(bp + DN_B + dB, Bw + bo, 16);
    };

    float acc[4][4][4];
#pragma unroll
    for (int i = 0; i < 4; i++)
#pragma unroll
        for (int j = 0; j < 4; j++)
#pragma unroll
            for (int q = 0; q < 4; q++) acc[i][j][q] = 0.f;

    const int mw = (wid >> 1) * 64;
    const int nw = (wid & 1) * 32;
    const int arow_off = ((lane >> 3) & 1) * 8 + (lane & 7);
    const int akb_off = (lane >> 4) * 16;
    const int kloc = (lane & 7) + ((lane >> 3) & 1) * 8;
    const int noff = (lane >> 4) * 8;

    uint32_t aoff[4][2], boff[2][2];
#pragma unroll
    for (int i = 0; i < 4; i++)
#pragma unroll
        for (int kk = 0; kk < 2; kk++)
            aoff[i][kk] = SWZ64((mw + i * 16 + arow_off) * 64 + kk * 32 + akb_off);
#pragma unroll
    for (int jp = 0; jp < 2; jp++)
#pragma unroll
        for (int kk = 0; kk < 2; kk++)
            boff[jp][kk] = SWZ128((kk * 16 + kloc) * 128 + (nw + jp * 16 + noff) * 2);

    auto compute_stage = [&](int st) {
        const uint32_t bp = sb + st * DN_STAGE;
#pragma unroll
        for (int kk = 0; kk < 2; kk++) {
            uint32_t a[4][4];
            uint32_t bb[2][4];
#pragma unroll
            for (int jp = 0; jp < 2; jp++)
                ldsm_x4t(bb[jp][0], bb[jp][1], bb[jp][2], bb[jp][3], bp + DN_B + boff[jp][kk]);
#pragma unroll
            for (int i = 0; i < 4; i++)
                ldsm_x4(a[i][0], a[i][1], a[i][2], a[i][3], bp + DN_A + aoff[i][kk]);
#pragma unroll
            for (int i = 0; i < 4; i++)
#pragma unroll
                for (int jp = 0; jp < 2; jp++) {
                    mma_f16(acc[i][jp * 2 + 0], a[i], bb[jp][0], bb[jp][1]);
                    mma_f16(acc[i][jp * 2 + 1], a[i], bb[jp][2], bb[jp][3]);
                }
        }
    };

    const int NC = I / 32;
    load_stage(0, 0); CP_COMMIT();
    load_stage(1, 1); CP_COMMIT();
    for (int c = 0; c < NC; c += 2) {
        CP_WAIT0();
        __syncthreads();
        if (c + 2 < NC) { load_stage((c + 2) & 3, c + 2); CP_COMMIT(); }
        compute_stage(c & 3);
        if (c + 3 < NC) { load_stage((c + 3) & 3, c + 3); CP_COMMIT(); }
        compute_stage((c + 1) & 3);
    }

    const int r4 = lane >> 2;
    const int cp2 = (lane & 3) * 2;
#pragma unroll
    for (int i = 0; i < 4; i++)
#pragma unroll
        for (int hh = 0; hh < 2; hh++) {
            int row = mw + i * 16 + r4 + hh * 8;
            int slot = m0 + row;
            if (slot >= cnt) continue;
            int tok = tokSm[row];
            float w = wSm[row];
            float* dst = out + (size_t)tok * H;
#pragma unroll
            for (int j = 0; j < 4; j++) {
                int col = n0 + nw + (j >> 1) * 16 + (j & 1) * 8 + cp2;
                red_add_v2(dst + col, w * acc[i][j][hh * 2 + 0],
                                      w * acc[i][j][hh * 2 + 1]);
            }
        }
}

// ======================= launch =============================================
extern "C" void kernel_launch(void* const* d_in, const int* in_sizes, int n_in,
                              void* d_out, int out_size) {
    const float* x   = (const float*)d_in[0];
    const float* rw  = (const float*)d_in[1];
    const float* gw  = (const float*)d_in[2];
    const float* uw  = (const float*)d_in[3];
    const float* dw  = (const float*)d_in[4];
    const float* sgw = (const float*)d_in[5];
    const float* suw = (const float*)d_in[6];
    const float* sdw = (const float*)d_in[7];
    float* out = (float*)d_out;

    static bool s_init = false;
    static cudaStream_t s2;
    static cudaEvent_t evF, evGU, evD;
    if (!s_init) {
        cudaStreamCreateWithFlags(&s2, cudaStreamNonBlocking);
        cudaEventCreateWithFlags(&evF, cudaEventDisableTiming);
        cudaEventCreateWithFlags(&evGU, cudaEventDisableTiming);
        cudaEventCreateWithFlags(&evD, cudaEventDisableTiming);
        cudaFuncSetAttribute(mm_gateup_kernel,
                             cudaFuncAttributeMaxDynamicSharedMemorySize, GU_SMEM);
        cudaFuncSetAttribute(mm_down_kernel,
                             cudaFuncAttributeMaxDynamicSharedMemorySize, DN_SMEM);
        s_init = true;
    }

    init_kernel<<<1, 32>>>();

    // fork: out-zeroing + weight conversions on s2
    cudaEventRecord(evF, 0);
    cudaStreamWaitEvent(s2, evF, 0);
    cudaMemsetAsync(out, 0, (size_t)T * H * sizeof(float), s2);
    prep_w_gu_kernel<<<GUW_BLK, 256, 0, s2>>>(gw, uw, sgw, suw);
    cudaEventRecord(evGU, s2);
    prep_w_d_kernel<<<DW_BLK, 256, 0, s2>>>(dw, sdw);
    cudaEventRecord(evD, s2);   // evD also implies memset complete (stream order)

    // main: x convert, router, finalize
    xconv_kernel<<<(T * H / 8) / 512, 256>>>(x);
    router_kernel<<<T / 8, 256>>>(x, rw, out);
    finalize_kernel<<<1, 32>>>(out);

    cudaStreamWaitEvent(0, evGU, 0);
    mm_gateup_kernel<<<dim3(I / 64, T / 128, E + 1), 256, GU_SMEM>>>();
    cudaStreamWaitEvent(0, evD, 0);
    mm_down_kernel<<<dim3(H / 64, T / 256, E + 1), 256, DN_SMEM>>>(out);
}